// round 7
// baseline (speedup 1.0000x reference)
#include <cuda_runtime.h>
#include <cuda_bf16.h>
#include <math.h>
#include <stdint.h>

#define B   8
#define D   384
#define FD  256
#define NP  4096
#define NH  8
#define NC  4
#define HD  48
#define GS  1024
#define T   (B*NP)     /* 32768 tokens */
#define D4  1536
#define D2  768
#define QS  1152       /* packed qkv row stride */

typedef __nv_bfloat16 bf16;
typedef __nv_bfloat162 bf162;

// ---------------- scratch (device globals) ----------------------------------
static __device__ float g_gb1[B*D2];
static __device__ float g_gb2[B*D2];
static __device__ float g_gx[B*D];
static __device__ float g_gm[B];
static __device__ float g_A2[B*D];
static __device__ float g_C2[B*D];
static __device__ float g_gx2sq[B*D];
static __device__ int   g_invp[NP];
static __device__ float g_imtok[(size_t)T*D];
static __device__ float g_wi[(size_t)T*D];
static __device__ float g_wif[(size_t)T*D];
static __device__ float g_kv[B*NC*NH*HD*HD];
static __device__ float g_ks[B*NC*NH*HD];
static __device__ float g_bqkv[QS];
// bf16 activations
static __device__ bf16  g_qkv16[(size_t)T*QS];
static __device__ bf16  g_xg16[(size_t)T*D];
static __device__ bf16  g_att16[(size_t)T*D];
static __device__ bf16  g_x216[(size_t)T*D];
static __device__ bf16  g_h116[(size_t)T*D4];
// bf16 weights
static __device__ bf16  g_wqkv16[QS*D];
static __device__ bf16  g_wo16[D*D];
static __device__ bf16  g_c1w16[D4*D];
static __device__ bf16  g_c2w16[D*D4];

// ---------------- helpers ----------------------------------------------------
__device__ __forceinline__ uint32_t sptr(const void* p) {
    return (uint32_t)__cvta_generic_to_shared(p);
}
__device__ __forceinline__ void cp16(uint32_t s, const void* g) {
    asm volatile("cp.async.cg.shared.global [%0], [%1], 16;\n" :: "r"(s), "l"(g));
}
__device__ __forceinline__ void cp_commit() {
    asm volatile("cp.async.commit_group;\n");
}
template<int N>
__device__ __forceinline__ void cp_wait() {
    asm volatile("cp.async.wait_group %0;\n" :: "n"(N));
}
__device__ __forceinline__ void mma16816(float* c, const uint32_t* a, const uint32_t* b) {
    asm volatile(
        "mma.sync.aligned.m16n8k16.row.col.f32.bf16.bf16.f32 "
        "{%0,%1,%2,%3}, {%4,%5,%6,%7}, {%8,%9}, {%0,%1,%2,%3};\n"
        : "+f"(c[0]), "+f"(c[1]), "+f"(c[2]), "+f"(c[3])
        : "r"(a[0]), "r"(a[1]), "r"(a[2]), "r"(a[3]), "r"(b[0]), "r"(b[1]));
}
__device__ __forceinline__ void ldsm4(uint32_t* r, uint32_t a) {
    asm volatile("ldmatrix.sync.aligned.m8n8.x4.shared.b16 {%0,%1,%2,%3}, [%4];"
        : "=r"(r[0]), "=r"(r[1]), "=r"(r[2]), "=r"(r[3]) : "r"(a));
}

__device__ __forceinline__ float blockReduce384(float v, float* sdata) {
    int tid = threadIdx.x;
    sdata[tid] = v;
    if (tid < 128) sdata[384 + tid] = 0.f;
    __syncthreads();
    #pragma unroll
    for (int s = 256; s >= 1; s >>= 1) {
        if (tid < s) sdata[tid] += sdata[tid + s];
        __syncthreads();
    }
    float r = sdata[0];
    __syncthreads();
    return r;
}

// ---------------- launch 0: prep (weights/bias/zero/invperm) + film ----------
#define NWQKV (3*D*D)
#define NWO   (D*D)
#define NC1   (D4*D)
#define NC2   (D*D4)
#define NFILM (2*B*D2)
#define PREP_TOT (NWQKV + NWO + NC1 + NC2 + QS + B*D + B + NP + NFILM)
__global__ void k_prep(const float* __restrict__ Wq, const float* __restrict__ Wk,
                       const float* __restrict__ Wv, const float* __restrict__ Wo,
                       const float* __restrict__ c1, const float* __restrict__ c2,
                       const float* __restrict__ bq, const float* __restrict__ bk,
                       const float* __restrict__ bv,
                       const int* __restrict__ perm,
                       const float* __restrict__ film,
                       const float* __restrict__ W1, const float* __restrict__ b1,
                       const float* __restrict__ W2, const float* __restrict__ b2,
                       bf16* __restrict__ wqkv, bf16* __restrict__ wo,
                       bf16* __restrict__ c1o, bf16* __restrict__ c2o,
                       float* __restrict__ bqkv, float* __restrict__ gx2sq,
                       float* __restrict__ gm, int* __restrict__ invp,
                       float* __restrict__ gb1, float* __restrict__ gb2) {
    int i = blockIdx.x * blockDim.x + threadIdx.x;
    if (i < NWQKV) {
        int seg = i / (D*D), r = i % (D*D);
        const float* W = (seg == 0) ? Wq : (seg == 1) ? Wk : Wv;
        wqkv[i] = __float2bfloat16(W[r]);
        return;
    }
    i -= NWQKV;
    if (i < NWO) { wo[i] = __float2bfloat16(Wo[i]); return; }
    i -= NWO;
    if (i < NC1) { c1o[i] = __float2bfloat16(c1[i]); return; }
    i -= NC1;
    if (i < NC2) { c2o[i] = __float2bfloat16(c2[i]); return; }
    i -= NC2;
    if (i < QS) {
        bqkv[i] = (i < D) ? bq[i] : (i < 2*D) ? bk[i - D] : bv[i - 2*D];
        return;
    }
    i -= QS;
    if (i < B*D) { gx2sq[i] = 0.f; return; }
    i -= B*D;
    if (i < B) { gm[i] = 0.f; return; }
    i -= B;
    if (i < NP) { invp[perm[i]] = i; return; }
    i -= NP;
    if (i < NFILM) {
        int which = i / (B * D2);
        int r = i % (B * D2);
        int b = r / D2, j = r % D2;
        const float* W = which ? W2 : W1;
        const float* bb = which ? b2 : b1;
        const float* f = film + b * FD;
        const float* w = W + (size_t)j * FD;
        float s = 0.f;
        #pragma unroll 8
        for (int q = 0; q < FD; q++) s += f[q] * w[q];
        s += bb[j];
        if (which) gb2[r] = s; else gb1[r] = s;
    }
}

// ---------------- launch 1: per-(b,d) L2 norm + atomic batch-mean ------------
__global__ void k_gx_img(const float* __restrict__ img, float* __restrict__ gx,
                         float* __restrict__ gm) {
    __shared__ float sdata[256];
    int bd = blockIdx.x;
    const float* p = img + (size_t)bd * NP;
    float s = 0.f;
    for (int i = threadIdx.x; i < NP; i += 256) { float v = p[i]; s += v * v; }
    sdata[threadIdx.x] = s; __syncthreads();
    for (int st = 128; st >= 1; st >>= 1) {
        if (threadIdx.x < st) sdata[threadIdx.x] += sdata[threadIdx.x + st];
        __syncthreads();
    }
    if (threadIdx.x == 0) {
        float g = sqrtf(sdata[0]);
        gx[bd] = g;
        atomicAdd(&gm[bd / D], g * (1.f / (float)D));
    }
}

// gmean+coef for GRN2 (input gx2sq needs sqrt)
__global__ void k_gmean_coef(const float* __restrict__ gxsq,
                             const float* __restrict__ gg, const float* __restrict__ gb_,
                             const float* __restrict__ gbmat,
                             float* __restrict__ A, float* __restrict__ C) {
    __shared__ float sdata[512];
    int b = blockIdx.x, d = threadIdx.x;
    float gv = sqrtf(gxsq[b * D + d]);
    float s = blockReduce384(gv, sdata);
    float gm = s / (float)D;
    float nx = gv / (gm + 1e-6f);
    float gamma = gbmat[b * D2 + d];
    float beta  = gbmat[b * D2 + D + d];
    A[b * D + d] = ((1.f + gg[d]) * nx + 1.f) * (1.f + gamma);
    C[b * D + d] = gb_[d] * (1.f + gamma) + beta;
}

// ---------------- launch 2: transpose-gather with inline adaLN1 coef ---------
__global__ void __launch_bounds__(256) k_gather_t(
        const float* __restrict__ img, const int* __restrict__ invp,
        const float* __restrict__ gx, const float* __restrict__ gm,
        const float* __restrict__ gg, const float* __restrict__ gb_,
        const float* __restrict__ gb1,
        float* __restrict__ imtok, bf16* __restrict__ xg) {
    __shared__ float tile[64][65];
    __shared__ float sA[64], sC[64];
    __shared__ int sinv[64];
    int p0 = blockIdx.x * 64, d0 = blockIdx.y * 64, b = blockIdx.z;
    int tid = threadIdx.x;
    if (tid < 64) sinv[tid] = invp[p0 + tid];
    else if (tid >= 64 && tid < 128) {
        int dl = tid - 64, d = d0 + dl;
        float nx = gx[b * D + d] / (gm[b] + 1e-6f);
        float gamma = gb1[b * D2 + d];
        float beta  = gb1[b * D2 + D + d];
        sA[dl] = ((1.f + gg[d]) * nx + 1.f) * (1.f + gamma);
        sC[dl] = gb_[d] * (1.f + gamma) + beta;
    }
    #pragma unroll
    for (int l = 0; l < 4; l++) {
        int j = tid + l * 256;
        int i = j >> 4, q = (j & 15) * 4;
        float4 v = *(const float4*)(img + ((size_t)(b * D + d0 + i)) * NP + p0 + q);
        tile[i][q + 0] = v.x; tile[i][q + 1] = v.y;
        tile[i][q + 2] = v.z; tile[i][q + 3] = v.w;
    }
    __syncthreads();
    #pragma unroll
    for (int l = 0; l < 4; l++) {
        int j = tid + l * 256;
        int jp = j >> 4, i4 = (j & 15) * 4;
        int t = sinv[jp];
        size_t o = ((size_t)(b * NP + t)) * D + d0 + i4;
        float vv[4], xv[4];
        #pragma unroll
        for (int r = 0; r < 4; r++) {
            vv[r] = tile[i4 + r][jp];
            xv[r] = sA[i4 + r] * vv[r] + sC[i4 + r];
        }
        *(float4*)&imtok[o] = make_float4(vv[0], vv[1], vv[2], vv[3]);
        *(bf162*)&xg[o] = __floats2bfloat162_rn(xv[0], xv[1]);
        *(bf162*)&xg[o + 2] = __floats2bfloat162_rn(xv[2], xv[3]);
    }
}

// ---------------- bf16 tensor-core GEMM (ldmatrix + 3-stage, 1 sync/iter) ----
#define LDT 40
#define STG 3
#define STAGE_E (128 * LDT)
#define GEMM_SMEM (STG * 2 * STAGE_E * 2)
template<typename OutT, bool SILU, bool RES, bool GX2>
__global__ void __launch_bounds__(256, 2) gemm_mma(
        const bf16* __restrict__ A, const bf16* __restrict__ W,
        const float* __restrict__ bias, const float* __restrict__ res,
        const float* __restrict__ scale, OutT* __restrict__ C,
        float* __restrict__ gx2sq, int M, int N, int K) {
    extern __shared__ bf16 smem[];
    bf16* sA = smem;
    bf16* sW = smem + STG * STAGE_E;
    uint32_t sbA = sptr(sA), sbW = sptr(sW);
    int tid = threadIdx.x;
    int m0 = blockIdx.y * 128, n0 = blockIdx.x * 128;
    int lane = tid & 31, warp = tid >> 5;
    int g = lane >> 2, tg = lane & 3;
    int wm = warp >> 2, wn = warp & 3;
    int lane8 = lane & 7, laneg = lane >> 3;

    uint32_t aOff[4], bOff[2];
    #pragma unroll
    for (int im = 0; im < 4; im++) {
        int row = wm * 64 + im * 16 + lane8 + (laneg & 1) * 8;
        int col = (laneg >> 1) * 8;
        aOff[im] = (uint32_t)(row * LDT + col) * 2;
    }
    #pragma unroll
    for (int p = 0; p < 2; p++) {
        int row = wn * 32 + p * 16 + lane8 + (laneg >> 1) * 8;
        int col = (laneg & 1) * 8;
        bOff[p] = (uint32_t)(row * LDT + col) * 2;
    }

    float acc[4][4][4];
    #pragma unroll
    for (int i = 0; i < 4; i++)
        #pragma unroll
        for (int j = 0; j < 4; j++)
            #pragma unroll
            for (int p = 0; p < 4; p++) acc[i][j][p] = 0.f;

    int nt = K / 32;
    auto issue = [&](int t) {
        if (t < nt) {
            int s = t % STG;
            int k0 = t * 32;
            #pragma unroll
            for (int l = 0; l < 2; l++) {
                int j = tid + l * 256;
                int row = j >> 2, q = (j & 3) * 8;
                cp16(sbA + (s * STAGE_E + row * LDT + q) * 2, A + (size_t)(m0 + row) * K + k0 + q);
                cp16(sbW + (s * STAGE_E + row * LDT + q) * 2, W + (size_t)(n0 + row) * K + k0 + q);
            }
        }
        cp_commit();
    };

    issue(0);
    issue(1);
    for (int t = 0; t < nt; t++) {
        cp_wait<STG - 2>();
        __syncthreads();          // single barrier per iteration (3-stage safe)
        int s = t % STG;
        uint32_t aBase = sbA + s * STAGE_E * 2;
        uint32_t wBase = sbW + s * STAGE_E * 2;
        #pragma unroll
        for (int kk = 0; kk < 32; kk += 16) {
            uint32_t af[4][4], bf[2][4];
            #pragma unroll
            for (int im = 0; im < 4; im++) ldsm4(af[im], aBase + aOff[im] + kk * 2);
            #pragma unroll
            for (int p = 0; p < 2; p++)    ldsm4(bf[p], wBase + bOff[p] + kk * 2);
            #pragma unroll
            for (int im = 0; im < 4; im++)
                #pragma unroll
                for (int in = 0; in < 4; in++)
                    mma16816(acc[im][in], af[im], &bf[in >> 1][(in & 1) * 2]);
        }
        issue(t + 2);
    }

    // epilogue
    float sums[4][2];
    if (GX2) {
        #pragma unroll
        for (int in = 0; in < 4; in++) { sums[in][0] = 0.f; sums[in][1] = 0.f; }
    }
    #pragma unroll
    for (int im = 0; im < 4; im++) {
        int r0 = m0 + wm * 64 + im * 16 + g;
        #pragma unroll
        for (int in = 0; in < 4; in++) {
            int c = n0 + wn * 32 + in * 8 + tg * 2;
            float b0 = bias[c], b1 = bias[c + 1];
            float v00 = acc[im][in][0] + b0, v01 = acc[im][in][1] + b1;
            float v10 = acc[im][in][2] + b0, v11 = acc[im][in][3] + b1;
            if (SILU) {
                v00 = v00 / (1.f + expf(-v00)); v01 = v01 / (1.f + expf(-v01));
                v10 = v10 / (1.f + expf(-v10)); v11 = v11 / (1.f + expf(-v11));
            }
            if (RES) {
                float s0 = scale[c], s1 = scale[c + 1];
                float2 ra = *(const float2*)&res[(size_t)r0 * N + c];
                float2 rb = *(const float2*)&res[(size_t)(r0 + 8) * N + c];
                v00 = ra.x + v00 * s0; v01 = ra.y + v01 * s1;
                v10 = rb.x + v10 * s0; v11 = rb.y + v11 * s1;
            }
            if (GX2) {
                sums[in][0] += v00 * v00 + v10 * v10;
                sums[in][1] += v01 * v01 + v11 * v11;
            }
            if (sizeof(OutT) == 4) {
                *(float2*)((float*)C + (size_t)r0 * N + c) = make_float2(v00, v01);
                *(float2*)((float*)C + (size_t)(r0 + 8) * N + c) = make_float2(v10, v11);
            } else {
                *(bf162*)((bf16*)C + (size_t)r0 * N + c) = __floats2bfloat162_rn(v00, v01);
                *(bf162*)((bf16*)C + (size_t)(r0 + 8) * N + c) = __floats2bfloat162_rn(v10, v11);
            }
        }
    }
    if (GX2) {
        #pragma unroll
        for (int off = 4; off <= 16; off <<= 1) {
            #pragma unroll
            for (int in = 0; in < 4; in++) {
                sums[in][0] += __shfl_xor_sync(0xffffffff, sums[in][0], off);
                sums[in][1] += __shfl_xor_sync(0xffffffff, sums[in][1], off);
            }
        }
        if (lane < 4) {
            int b = m0 >> 12;
            #pragma unroll
            for (int in = 0; in < 4; in++) {
                int c = n0 + wn * 32 + in * 8 + tg * 2;
                atomicAdd(&gx2sq[b * D + c], sums[in][0]);
                atomicAdd(&gx2sq[b * D + c + 1], sums[in][1]);
            }
        }
    }
}

// per-token LayerNorm over D then elu+1, bf16 in/out, warp per token; y: 0=q, 1=k
__global__ void __launch_bounds__(256) k_lnelu(bf16* __restrict__ X,
        const float* __restrict__ gq, const float* __restrict__ bq_,
        const float* __restrict__ gk, const float* __restrict__ bk_) {
    int warp = threadIdx.x >> 5, lane = threadIdx.x & 31;
    int t = blockIdx.x * 8 + warp;
    int seg = blockIdx.y;
    const float* gam = seg ? gk : gq;
    const float* bet = seg ? bk_ : bq_;
    size_t base = (size_t)t * QS + seg * D;
    float v[12];
    float s = 0.f, s2 = 0.f;
    #pragma unroll
    for (int j = 0; j < 12; j++) {
        v[j] = __bfloat162float(X[base + j * 32 + lane]);
        s += v[j]; s2 += v[j] * v[j];
    }
    #pragma unroll
    for (int o = 16; o >= 1; o >>= 1) {
        s  += __shfl_xor_sync(0xffffffff, s, o);
        s2 += __shfl_xor_sync(0xffffffff, s2, o);
    }
    float mean = s / (float)D;
    float var = s2 / (float)D - mean * mean;
    float rstd = rsqrtf(var + 1e-5f);
    #pragma unroll
    for (int j = 0; j < 12; j++) {
        int d = j * 32 + lane;
        float y = (v[j] - mean) * rstd * gam[d] + bet[d];
        X[base + d] = __float2bfloat16((y > 0.f) ? (y + 1.f) : expf(y));
    }
}

// kv[bh] = sum_i k_i outer v_i ; ksum[bh] = sum_i k_i
__global__ void __launch_bounds__(256) k_attn_kv(const bf16* __restrict__ qkv,
                                                 float* __restrict__ kv,
                                                 float* __restrict__ ksum) {
    int bh = blockIdx.x;
    int h = bh & (NH - 1), bc = bh >> 3;
    __shared__ float sk[16][HD];
    __shared__ float sv[16][HD];
    int tid = threadIdx.x;
    float acc[9];
    #pragma unroll
    for (int p = 0; p < 9; p++) acc[p] = 0.f;
    float ks = 0.f;
    int base = tid * 9;
    int dp[9], ep[9];
    #pragma unroll
    for (int p = 0; p < 9; p++) { dp[p] = (base + p) / HD; ep[p] = (base + p) % HD; }

    for (int c = 0; c < GS / 16; c++) {
        int tt0 = bc * GS + c * 16;
        #pragma unroll
        for (int r = 0; r < 3; r++) {
            int j = r * 256 + tid;
            int ti = j / HD, d = j % HD;
            size_t row = (size_t)(tt0 + ti) * QS + h * HD + d;
            sk[ti][d] = __bfloat162float(qkv[row + D]);
            sv[ti][d] = __bfloat162float(qkv[row + 2 * D]);
        }
        __syncthreads();
        #pragma unroll 4
        for (int ti = 0; ti < 16; ti++) {
            #pragma unroll
            for (int p = 0; p < 9; p++) acc[p] += sk[ti][dp[p]] * sv[ti][ep[p]];
        }
        if (tid < HD) {
            #pragma unroll 4
            for (int ti = 0; ti < 16; ti++) ks += sk[ti][tid];
        }
        __syncthreads();
    }
    #pragma unroll
    for (int p = 0; p < 9; p++) kv[(size_t)bh * HD * HD + base + p] = acc[p];
    if (tid < HD) ksum[bh * HD + tid] = ks;
}

// out[t,h,e] = (q . kv[:,e]) / (q . ksum + 1e-8), bf16 output
__global__ void __launch_bounds__(256) k_attn_apply(const bf16* __restrict__ qkv,
                                                    const float* __restrict__ kv,
                                                    const float* __restrict__ ksum,
                                                    bf16* __restrict__ out) {
    int bh = blockIdx.x;
    int tile = blockIdx.y;
    int h = bh & (NH - 1), bc = bh >> 3;
    __shared__ float skv[HD * HD];
    __shared__ float sks[HD];
    __shared__ float sq[16][HD];
    int tid = threadIdx.x;
    for (int i = tid; i < HD * HD; i += 256) skv[i] = kv[(size_t)bh * HD * HD + i];
    if (tid < HD) sks[tid] = ksum[bh * HD + tid];
    __syncthreads();
    int t0 = bc * GS + tile * 64;
    for (int sub = 0; sub < 4; sub++) {
        int tt0 = t0 + sub * 16;
        #pragma unroll
        for (int r = 0; r < 3; r++) {
            int j = r * 256 + tid;
            int ti = j / HD, d = j % HD;
            sq[ti][d] = __bfloat162float(qkv[(size_t)(tt0 + ti) * QS + h * HD + d]);
        }
        __syncthreads();
        #pragma unroll
        for (int r = 0; r < 3; r++) {
            int j = r * 256 + tid;
            int ti = j / HD, e = j % HD;
            float num = 0.f, den = 0.f;
            #pragma unroll
            for (int d = 0; d < HD; d++) {
                float qq = sq[ti][d];
                num += qq * skv[d * HD + e];
                den += qq * sks[d];
            }
            out[(size_t)(tt0 + ti) * D + h * HD + e] = __float2bfloat16(num / (den + 1e-8f));
        }
        __syncthreads();
    }
}

// x2 = A2[b,d]*wi + C2[b,d], bf16 output
__global__ void k_x2(const float* __restrict__ wi, const float* __restrict__ A,
                     const float* __restrict__ C, bf16* __restrict__ x2) {
    size_t idx = (size_t)blockIdx.x * 256 + threadIdx.x;
    int t = (int)(idx / D), d = (int)(idx % D);
    int b = t >> 12;
    x2[idx] = __float2bfloat16(A[b * D + d] * wi[idx] + C[b * D + d]);
}

// out[b,d,pix] = image[b,d,pix] + wif[token(pix), d] * final_scalar[d]
__global__ void __launch_bounds__(256) k_final_t(
        const float* __restrict__ img, const float* __restrict__ wif,
        const int* __restrict__ invp, const float* __restrict__ fs,
        float* __restrict__ out) {
    __shared__ float tile[64][65];
    __shared__ int sinv[64];
    int p0 = blockIdx.x * 64, d0 = blockIdx.y * 64, b = blockIdx.z;
    int tid = threadIdx.x;
    if (tid < 64) sinv[tid] = invp[p0 + tid];
    __syncthreads();
    #pragma unroll
    for (int l = 0; l < 4; l++) {
        int j = tid + l * 256;
        int jp = j >> 4, i4 = (j & 15) * 4;
        int t = sinv[jp];
        float4 v = *(const float4*)(wif + ((size_t)(b * NP + t)) * D + d0 + i4);
        tile[i4 + 0][jp] = v.x; tile[i4 + 1][jp] = v.y;
        tile[i4 + 2][jp] = v.z; tile[i4 + 3][jp] = v.w;
    }
    __syncthreads();
    #pragma unroll
    for (int l = 0; l < 4; l++) {
        int j = tid + l * 256;
        int i = j >> 4, q = (j & 15) * 4;
        size_t o = ((size_t)(b * D + d0 + i)) * NP + p0 + q;
        float4 im4 = *(const float4*)(img + o);
        float f = fs[d0 + i];
        float4 r;
        r.x = im4.x + tile[i][q + 0] * f;
        r.y = im4.y + tile[i][q + 1] * f;
        r.z = im4.z + tile[i][q + 2] * f;
        r.w = im4.w + tile[i][q + 3] * f;
        *(float4*)(out + o) = r;
    }
}

// ---------------- driver ----------------------------------------------------
extern "C" void kernel_launch(void* const* d_in, const int* in_sizes, int n_in,
                              void* d_out, int out_size) {
    const float* image  = (const float*)d_in[0];
    const float* film   = (const float*)d_in[1];
    const int*   perm   = (const int*)d_in[2];
    const float* Wq = (const float*)d_in[3];  const float* bq = (const float*)d_in[4];
    const float* Wk = (const float*)d_in[5];  const float* bk = (const float*)d_in[6];
    const float* Wv = (const float*)d_in[7];  const float* bv = (const float*)d_in[8];
    const float* Wo = (const float*)d_in[9];  const float* bo = (const float*)d_in[10];
    const float* lnq_g = (const float*)d_in[11]; const float* lnq_b = (const float*)d_in[12];
    const float* lnk_g = (const float*)d_in[13]; const float* lnk_b = (const float*)d_in[14];
    const float* ada1_W = (const float*)d_in[15]; const float* ada1_b = (const float*)d_in[16];
    const float* grn1_g = (const float*)d_in[17]; const float* grn1_b = (const float*)d_in[18];
    const float* ada2_W = (const float*)d_in[19]; const float* ada2_b = (const float*)d_in[20];
    const float* grn2_g = (const float*)d_in[21]; const float* grn2_b = (const float*)d_in[22];
    const float* conv1_W = (const float*)d_in[23]; const float* conv1_b = (const float*)d_in[24];
    const float* conv2_W = (const float*)d_in[25]; const float* conv2_b = (const float*)d_in[26];
    const float* cs  = (const float*)d_in[27];
    const float* ffs = (const float*)d_in[28];
    const float* fs  = (const float*)d_in[29];
    float* out = (float*)d_out;

    float *p_gb1, *p_gb2, *p_gx, *p_gm, *p_A2, *p_C2, *p_gx2sq;
    int* p_invp;
    float *p_imtok, *p_wi, *p_wif, *p_kv, *p_ks, *p_bqkv;
    bf16 *p_qkv16, *p_xg16, *p_att16, *p_x216, *p_h116;
    bf16 *p_wqkv16, *p_wo16, *p_c1w16, *p_c2w16;
    cudaGetSymbolAddress((void**)&p_gb1, g_gb1);
    cudaGetSymbolAddress((void**)&p_gb2, g_gb2);
    cudaGetSymbolAddress((void**)&p_gx, g_gx);
    cudaGetSymbolAddress((void**)&p_gm, g_gm);
    cudaGetSymbolAddress((void**)&p_A2, g_A2);
    cudaGetSymbolAddress((void**)&p_C2, g_C2);
    cudaGetSymbolAddress((void**)&p_gx2sq, g_gx2sq);
    cudaGetSymbolAddress((void**)&p_invp, g_invp);
    cudaGetSymbolAddress((void**)&p_imtok, g_imtok);
    cudaGetSymbolAddress((void**)&p_wi, g_wi);
    cudaGetSymbolAddress((void**)&p_wif, g_wif);
    cudaGetSymbolAddress((void**)&p_kv, g_kv);
    cudaGetSymbolAddress((void**)&p_ks, g_ks);
    cudaGetSymbolAddress((void**)&p_bqkv, g_bqkv);
    cudaGetSymbolAddress((void**)&p_qkv16, g_qkv16);
    cudaGetSymbolAddress((void**)&p_xg16, g_xg16);
    cudaGetSymbolAddress((void**)&p_att16, g_att16);
    cudaGetSymbolAddress((void**)&p_x216, g_x216);
    cudaGetSymbolAddress((void**)&p_h116, g_h116);
    cudaGetSymbolAddress((void**)&p_wqkv16, g_wqkv16);
    cudaGetSymbolAddress((void**)&p_wo16, g_wo16);
    cudaGetSymbolAddress((void**)&p_c1w16, g_c1w16);
    cudaGetSymbolAddress((void**)&p_c2w16, g_c2w16);

    cudaFuncSetAttribute((const void*)gemm_mma<bf16,false,false,false>,
                         cudaFuncAttributeMaxDynamicSharedMemorySize, GEMM_SMEM);
    cudaFuncSetAttribute((const void*)gemm_mma<float,false,true,true>,
                         cudaFuncAttributeMaxDynamicSharedMemorySize, GEMM_SMEM);
    cudaFuncSetAttribute((const void*)gemm_mma<bf16,true,false,false>,
                         cudaFuncAttributeMaxDynamicSharedMemorySize, GEMM_SMEM);
    cudaFuncSetAttribute((const void*)gemm_mma<float,false,true,false>,
                         cudaFuncAttributeMaxDynamicSharedMemorySize, GEMM_SMEM);

    // launch 0: all prep + film
    k_prep<<<(PREP_TOT + 255) / 256, 256>>>(Wq, Wk, Wv, Wo, conv1_W, conv2_W,
        bq, bk, bv, perm, film, ada1_W, ada1_b, ada2_W, ada2_b,
        p_wqkv16, p_wo16, p_c1w16, p_c2w16,
        p_bqkv, p_gx2sq, p_gm, p_invp, p_gb1, p_gb2);
    // launch 1: gx + batch mean
    k_gx_img<<<B * D, 256>>>(image, p_gx, p_gm);
    // launch 2: gather with inline adaLN1 coefficients
    k_gather_t<<<dim3(NP/64, D/64, B), 256>>>(image, p_invp, p_gx, p_gm,
        grn1_g, grn1_b, p_gb1, p_imtok, p_xg16);
    // launch 3: packed QKV GEMM  <-- profiled launch
    gemm_mma<bf16,false,false,false><<<dim3(QS/128, T/128), 256, GEMM_SMEM>>>(
        p_xg16, p_wqkv16, p_bqkv, nullptr, nullptr, p_qkv16, nullptr, T, QS, D);

    k_lnelu<<<dim3(T/8, 2), 256>>>(p_qkv16, lnq_g, lnq_b, lnk_g, lnk_b);

    k_attn_kv<<<B * NC * NH, 256>>>(p_qkv16, p_kv, p_ks);
    k_attn_apply<<<dim3(B * NC * NH, 16), 256>>>(p_qkv16, p_kv, p_ks, p_att16);

    // wi = imtok + (attn@Wo^T + bo) * cs ; also gx2sq += wi^2
    gemm_mma<float,false,true,true><<<dim3(3, T/128), 256, GEMM_SMEM>>>(
        p_att16, p_wo16, bo, p_imtok, cs, p_wi, p_gx2sq, T, D, D);

    k_gmean_coef<<<B, 384>>>(p_gx2sq, grn2_g, grn2_b, p_gb2, p_A2, p_C2);
    k_x2<<<(int)(((size_t)T*D) / 256), 256>>>(p_wi, p_A2, p_C2, p_x216);

    // h1 = silu(x2 @ conv1^T + b1)
    gemm_mma<bf16,true,false,false><<<dim3(12, T/128), 256, GEMM_SMEM>>>(
        p_x216, p_c1w16, conv1_b, nullptr, nullptr, p_h116, nullptr, T, D4, D);
    // wif = wi + (h1 @ conv2^T + b2) * ffs
    gemm_mma<float,false,true,false><<<dim3(3, T/128), 256, GEMM_SMEM>>>(
        p_h116, p_c2w16, conv2_b, p_wi, ffs, p_wif, nullptr, T, D, D4);

    k_final_t<<<dim3(NP/64, D/64, B), 256>>>(image, p_wif, p_invp, fs, out);
}

// round 9
// speedup vs baseline: 1.5531x; 1.5531x over previous
#include <cuda_runtime.h>
#include <cuda_bf16.h>
#include <math.h>
#include <stdint.h>

#define B   8
#define D   384
#define FD  256
#define NP  4096
#define NH  8
#define NC  4
#define HD  48
#define GS  1024
#define T   (B*NP)     /* 32768 tokens */
#define D4  1536
#define D2  768
#define QS  1152       /* packed qkv row stride */

typedef __nv_bfloat16 bf16;
typedef __nv_bfloat162 bf162;

// ---------------- scratch (device globals) ----------------------------------
static __device__ float g_gb1[B*D2];
static __device__ float g_gb2[B*D2];
static __device__ float g_gx[B*D];
static __device__ float g_gm[B];
static __device__ float g_A2[B*D];
static __device__ float g_C2[B*D];
static __device__ float g_gx2sq[B*D];
static __device__ int   g_invp[NP];
static __device__ float g_imtok[(size_t)T*D];
static __device__ float g_wi[(size_t)T*D];
static __device__ float g_wif[(size_t)T*D];
static __device__ float g_kv[B*NC*NH*HD*HD];
static __device__ float g_ks[B*NC*NH*HD];
static __device__ float g_bqkv[QS];
// bf16 activations
static __device__ bf16  g_qkv16[(size_t)T*QS];
static __device__ bf16  g_xg16[(size_t)T*D];
static __device__ bf16  g_att16[(size_t)T*D];
static __device__ bf16  g_x216[(size_t)T*D];
static __device__ bf16  g_h116[(size_t)T*D4];
// bf16 weights
static __device__ bf16  g_wqkv16[QS*D];
static __device__ bf16  g_wo16[D*D];
static __device__ bf16  g_c1w16[D4*D];
static __device__ bf16  g_c2w16[D*D4];

// ---------------- helpers ----------------------------------------------------
__device__ __forceinline__ uint32_t sptr(const void* p) {
    return (uint32_t)__cvta_generic_to_shared(p);
}
__device__ __forceinline__ void cp16(uint32_t s, const void* g) {
    asm volatile("cp.async.cg.shared.global [%0], [%1], 16;\n" :: "r"(s), "l"(g));
}
__device__ __forceinline__ void cp_commit() {
    asm volatile("cp.async.commit_group;\n");
}
template<int N>
__device__ __forceinline__ void cp_wait() {
    asm volatile("cp.async.wait_group %0;\n" :: "n"(N));
}
__device__ __forceinline__ void mma16816(float* c, const uint32_t* a, const uint32_t* b) {
    asm volatile(
        "mma.sync.aligned.m16n8k16.row.col.f32.bf16.bf16.f32 "
        "{%0,%1,%2,%3}, {%4,%5,%6,%7}, {%8,%9}, {%0,%1,%2,%3};\n"
        : "+f"(c[0]), "+f"(c[1]), "+f"(c[2]), "+f"(c[3])
        : "r"(a[0]), "r"(a[1]), "r"(a[2]), "r"(a[3]), "r"(b[0]), "r"(b[1]));
}
__device__ __forceinline__ void ldsm4(uint32_t* r, uint32_t a) {
    asm volatile("ldmatrix.sync.aligned.m8n8.x4.shared.b16 {%0,%1,%2,%3}, [%4];"
        : "=r"(r[0]), "=r"(r[1]), "=r"(r[2]), "=r"(r[3]) : "r"(a));
}

__device__ __forceinline__ float blockReduce384(float v, float* sdata) {
    int tid = threadIdx.x;
    sdata[tid] = v;
    if (tid < 128) sdata[384 + tid] = 0.f;
    __syncthreads();
    #pragma unroll
    for (int s = 256; s >= 1; s >>= 1) {
        if (tid < s) sdata[tid] += sdata[tid + s];
        __syncthreads();
    }
    float r = sdata[0];
    __syncthreads();
    return r;
}

// ---------------- launch 0: prep (weights/bias/zero/invperm) + film ----------
#define NWQKV (3*D*D)
#define NWO   (D*D)
#define NC1   (D4*D)
#define NC2   (D*D4)
#define NFILM (2*B*D2)
#define PREP_TOT (NWQKV + NWO + NC1 + NC2 + QS + B*D + B + NP + NFILM)
__global__ void k_prep(const float* __restrict__ Wq, const float* __restrict__ Wk,
                       const float* __restrict__ Wv, const float* __restrict__ Wo,
                       const float* __restrict__ c1, const float* __restrict__ c2,
                       const float* __restrict__ bq, const float* __restrict__ bk,
                       const float* __restrict__ bv,
                       const int* __restrict__ perm,
                       const float* __restrict__ film,
                       const float* __restrict__ W1, const float* __restrict__ b1,
                       const float* __restrict__ W2, const float* __restrict__ b2,
                       bf16* __restrict__ wqkv, bf16* __restrict__ wo,
                       bf16* __restrict__ c1o, bf16* __restrict__ c2o,
                       float* __restrict__ bqkv, float* __restrict__ gx2sq,
                       float* __restrict__ gm, int* __restrict__ invp,
                       float* __restrict__ gb1, float* __restrict__ gb2) {
    int i = blockIdx.x * blockDim.x + threadIdx.x;
    if (i < NWQKV) {
        int seg = i / (D*D), r = i % (D*D);
        const float* W = (seg == 0) ? Wq : (seg == 1) ? Wk : Wv;
        wqkv[i] = __float2bfloat16(W[r]);
        return;
    }
    i -= NWQKV;
    if (i < NWO) { wo[i] = __float2bfloat16(Wo[i]); return; }
    i -= NWO;
    if (i < NC1) { c1o[i] = __float2bfloat16(c1[i]); return; }
    i -= NC1;
    if (i < NC2) { c2o[i] = __float2bfloat16(c2[i]); return; }
    i -= NC2;
    if (i < QS) {
        bqkv[i] = (i < D) ? bq[i] : (i < 2*D) ? bk[i - D] : bv[i - 2*D];
        return;
    }
    i -= QS;
    if (i < B*D) { gx2sq[i] = 0.f; return; }
    i -= B*D;
    if (i < B) { gm[i] = 0.f; return; }
    i -= B;
    if (i < NP) { invp[perm[i]] = i; return; }
    i -= NP;
    if (i < NFILM) {
        int which = i / (B * D2);
        int r = i % (B * D2);
        int b = r / D2, j = r % D2;
        const float* W = which ? W2 : W1;
        const float* bb = which ? b2 : b1;
        const float* f = film + b * FD;
        const float* w = W + (size_t)j * FD;
        float s = 0.f;
        #pragma unroll 8
        for (int q = 0; q < FD; q++) s += f[q] * w[q];
        s += bb[j];
        if (which) gb2[r] = s; else gb1[r] = s;
    }
}

// ---------------- launch 1: per-(b,d) L2 norm + atomic batch-mean ------------
__global__ void k_gx_img(const float* __restrict__ img, float* __restrict__ gx,
                         float* __restrict__ gm) {
    __shared__ float sdata[256];
    int bd = blockIdx.x;
    const float* p = img + (size_t)bd * NP;
    float s = 0.f;
    for (int i = threadIdx.x; i < NP; i += 256) { float v = p[i]; s += v * v; }
    sdata[threadIdx.x] = s; __syncthreads();
    for (int st = 128; st >= 1; st >>= 1) {
        if (threadIdx.x < st) sdata[threadIdx.x] += sdata[threadIdx.x + st];
        __syncthreads();
    }
    if (threadIdx.x == 0) {
        float g = sqrtf(sdata[0]);
        gx[bd] = g;
        atomicAdd(&gm[bd / D], g * (1.f / (float)D));
    }
}

// gmean+coef for GRN2 (input gx2sq needs sqrt)
__global__ void k_gmean_coef(const float* __restrict__ gxsq,
                             const float* __restrict__ gg, const float* __restrict__ gb_,
                             const float* __restrict__ gbmat,
                             float* __restrict__ A, float* __restrict__ C) {
    __shared__ float sdata[512];
    int b = blockIdx.x, d = threadIdx.x;
    float gv = sqrtf(gxsq[b * D + d]);
    float s = blockReduce384(gv, sdata);
    float gm = s / (float)D;
    float nx = gv / (gm + 1e-6f);
    float gamma = gbmat[b * D2 + d];
    float beta  = gbmat[b * D2 + D + d];
    A[b * D + d] = ((1.f + gg[d]) * nx + 1.f) * (1.f + gamma);
    C[b * D + d] = gb_[d] * (1.f + gamma) + beta;
}

// ---------------- launch 2: transpose-gather with inline adaLN1 coef ---------
__global__ void __launch_bounds__(256) k_gather_t(
        const float* __restrict__ img, const int* __restrict__ invp,
        const float* __restrict__ gx, const float* __restrict__ gm,
        const float* __restrict__ gg, const float* __restrict__ gb_,
        const float* __restrict__ gb1,
        float* __restrict__ imtok, bf16* __restrict__ xg) {
    __shared__ float tile[64][65];
    __shared__ float sA[64], sC[64];
    __shared__ int sinv[64];
    int p0 = blockIdx.x * 64, d0 = blockIdx.y * 64, b = blockIdx.z;
    int tid = threadIdx.x;
    if (tid < 64) sinv[tid] = invp[p0 + tid];
    else if (tid >= 64 && tid < 128) {
        int dl = tid - 64, d = d0 + dl;
        float nx = gx[b * D + d] / (gm[b] + 1e-6f);
        float gamma = gb1[b * D2 + d];
        float beta  = gb1[b * D2 + D + d];
        sA[dl] = ((1.f + gg[d]) * nx + 1.f) * (1.f + gamma);
        sC[dl] = gb_[d] * (1.f + gamma) + beta;
    }
    #pragma unroll
    for (int l = 0; l < 4; l++) {
        int j = tid + l * 256;
        int i = j >> 4, q = (j & 15) * 4;
        float4 v = *(const float4*)(img + ((size_t)(b * D + d0 + i)) * NP + p0 + q);
        tile[i][q + 0] = v.x; tile[i][q + 1] = v.y;
        tile[i][q + 2] = v.z; tile[i][q + 3] = v.w;
    }
    __syncthreads();
    #pragma unroll
    for (int l = 0; l < 4; l++) {
        int j = tid + l * 256;
        int jp = j >> 4, i4 = (j & 15) * 4;
        int t = sinv[jp];
        size_t o = ((size_t)(b * NP + t)) * D + d0 + i4;
        float vv[4], xv[4];
        #pragma unroll
        for (int r = 0; r < 4; r++) {
            vv[r] = tile[i4 + r][jp];
            xv[r] = sA[i4 + r] * vv[r] + sC[i4 + r];
        }
        *(float4*)&imtok[o] = make_float4(vv[0], vv[1], vv[2], vv[3]);
        *(bf162*)&xg[o] = __floats2bfloat162_rn(xv[0], xv[1]);
        *(bf162*)&xg[o + 2] = __floats2bfloat162_rn(xv[2], xv[3]);
    }
}

// ---------------- bf16 tensor-core GEMM (ldmatrix, BK=64, 2-stage) -----------
#define LDT 72
#define STG 2
#define STAGE_E (128 * LDT)
#define GEMM_SMEM (STG * 2 * STAGE_E * 2)
template<typename OutT, bool SILU, bool RES, bool GX2>
__global__ void __launch_bounds__(256, 2) gemm_mma(
        const bf16* __restrict__ A, const bf16* __restrict__ W,
        const float* __restrict__ bias, const float* __restrict__ res,
        const float* __restrict__ scale, OutT* __restrict__ C,
        float* __restrict__ gx2sq, int M, int N, int K) {
    extern __shared__ bf16 smem[];
    bf16* sA = smem;
    bf16* sW = smem + STG * STAGE_E;
    uint32_t sbA = sptr(sA), sbW = sptr(sW);
    int tid = threadIdx.x;
    int m0 = blockIdx.y * 128, n0 = blockIdx.x * 128;
    int lane = tid & 31, warp = tid >> 5;
    int g = lane >> 2, tg = lane & 3;
    int wm = warp >> 2, wn = warp & 3;
    int lane8 = lane & 7, laneg = lane >> 3;

    uint32_t aOff[4], bOff[2];
    #pragma unroll
    for (int im = 0; im < 4; im++) {
        int row = wm * 64 + im * 16 + lane8 + (laneg & 1) * 8;
        int col = (laneg >> 1) * 8;
        aOff[im] = (uint32_t)(row * LDT + col) * 2;
    }
    #pragma unroll
    for (int p = 0; p < 2; p++) {
        int row = wn * 32 + p * 16 + lane8 + (laneg >> 1) * 8;
        int col = (laneg & 1) * 8;
        bOff[p] = (uint32_t)(row * LDT + col) * 2;
    }

    float acc[4][4][4];
    #pragma unroll
    for (int i = 0; i < 4; i++)
        #pragma unroll
        for (int j = 0; j < 4; j++)
            #pragma unroll
            for (int p = 0; p < 4; p++) acc[i][j][p] = 0.f;

    int nt = K / 64;
    auto issue = [&](int t) {
        if (t < nt) {
            int s = t & 1;
            int k0 = t * 64;
            #pragma unroll
            for (int l = 0; l < 4; l++) {
                int j = tid + l * 256;                 // 0..1023
                int row = j >> 3, q = (j & 7) * 8;     // 128 rows x 8 chunks
                cp16(sbA + (s * STAGE_E + row * LDT + q) * 2, A + (size_t)(m0 + row) * K + k0 + q);
                cp16(sbW + (s * STAGE_E + row * LDT + q) * 2, W + (size_t)(n0 + row) * K + k0 + q);
            }
        }
        cp_commit();
    };

    issue(0);
    for (int t = 0; t < nt; t++) {
        issue(t + 1);
        cp_wait<1>();
        __syncthreads();
        int s = t & 1;
        uint32_t aBase = sbA + s * STAGE_E * 2;
        uint32_t wBase = sbW + s * STAGE_E * 2;
        #pragma unroll
        for (int kk = 0; kk < 64; kk += 16) {
            uint32_t af[4][4], bf[2][4];
            #pragma unroll
            for (int im = 0; im < 4; im++) ldsm4(af[im], aBase + aOff[im] + kk * 2);
            #pragma unroll
            for (int p = 0; p < 2; p++)    ldsm4(bf[p], wBase + bOff[p] + kk * 2);
            #pragma unroll
            for (int im = 0; im < 4; im++)
                #pragma unroll
                for (int in = 0; in < 4; in++)
                    mma16816(acc[im][in], af[im], &bf[in >> 1][(in & 1) * 2]);
        }
        __syncthreads();
    }

    // epilogue
    float sums[4][2];
    if (GX2) {
        #pragma unroll
        for (int in = 0; in < 4; in++) { sums[in][0] = 0.f; sums[in][1] = 0.f; }
    }
    #pragma unroll
    for (int im = 0; im < 4; im++) {
        int r0 = m0 + wm * 64 + im * 16 + g;
        #pragma unroll
        for (int in = 0; in < 4; in++) {
            int c = n0 + wn * 32 + in * 8 + tg * 2;
            float b0 = bias[c], b1 = bias[c + 1];
            float v00 = acc[im][in][0] + b0, v01 = acc[im][in][1] + b1;
            float v10 = acc[im][in][2] + b0, v11 = acc[im][in][3] + b1;
            if (SILU) {
                v00 = v00 / (1.f + expf(-v00)); v01 = v01 / (1.f + expf(-v01));
                v10 = v10 / (1.f + expf(-v10)); v11 = v11 / (1.f + expf(-v11));
            }
            if (RES) {
                float s0 = scale[c], s1 = scale[c + 1];
                float2 ra = *(const float2*)&res[(size_t)r0 * N + c];
                float2 rb = *(const float2*)&res[(size_t)(r0 + 8) * N + c];
                v00 = ra.x + v00 * s0; v01 = ra.y + v01 * s1;
                v10 = rb.x + v10 * s0; v11 = rb.y + v11 * s1;
            }
            if (GX2) {
                sums[in][0] += v00 * v00 + v10 * v10;
                sums[in][1] += v01 * v01 + v11 * v11;
            }
            if (sizeof(OutT) == 4) {
                *(float2*)((float*)C + (size_t)r0 * N + c) = make_float2(v00, v01);
                *(float2*)((float*)C + (size_t)(r0 + 8) * N + c) = make_float2(v10, v11);
            } else {
                *(bf162*)((bf16*)C + (size_t)r0 * N + c) = __floats2bfloat162_rn(v00, v01);
                *(bf162*)((bf16*)C + (size_t)(r0 + 8) * N + c) = __floats2bfloat162_rn(v10, v11);
            }
        }
    }
    if (GX2) {
        #pragma unroll
        for (int off = 4; off <= 16; off <<= 1) {
            #pragma unroll
            for (int in = 0; in < 4; in++) {
                sums[in][0] += __shfl_xor_sync(0xffffffff, sums[in][0], off);
                sums[in][1] += __shfl_xor_sync(0xffffffff, sums[in][1], off);
            }
        }
        if (lane < 4) {
            int b = m0 >> 12;
            #pragma unroll
            for (int in = 0; in < 4; in++) {
                int c = n0 + wn * 32 + in * 8 + tg * 2;
                atomicAdd(&gx2sq[b * D + c], sums[in][0]);
                atomicAdd(&gx2sq[b * D + c + 1], sums[in][1]);
            }
        }
    }
}

// per-token LayerNorm over D then elu+1, bf16 in/out, warp per token; y: 0=q, 1=k
__global__ void __launch_bounds__(256) k_lnelu(bf16* __restrict__ X,
        const float* __restrict__ gq, const float* __restrict__ bq_,
        const float* __restrict__ gk, const float* __restrict__ bk_) {
    int warp = threadIdx.x >> 5, lane = threadIdx.x & 31;
    int t = blockIdx.x * 8 + warp;
    int seg = blockIdx.y;
    const float* gam = seg ? gk : gq;
    const float* bet = seg ? bk_ : bq_;
    size_t base = (size_t)t * QS + seg * D;
    float v[12];
    float s = 0.f, s2 = 0.f;
    #pragma unroll
    for (int j = 0; j < 12; j++) {
        v[j] = __bfloat162float(X[base + j * 32 + lane]);
        s += v[j]; s2 += v[j] * v[j];
    }
    #pragma unroll
    for (int o = 16; o >= 1; o >>= 1) {
        s  += __shfl_xor_sync(0xffffffff, s, o);
        s2 += __shfl_xor_sync(0xffffffff, s2, o);
    }
    float mean = s / (float)D;
    float var = s2 / (float)D - mean * mean;
    float rstd = rsqrtf(var + 1e-5f);
    #pragma unroll
    for (int j = 0; j < 12; j++) {
        int d = j * 32 + lane;
        float y = (v[j] - mean) * rstd * gam[d] + bet[d];
        X[base + d] = __float2bfloat16((y > 0.f) ? (y + 1.f) : expf(y));
    }
}

// kv[bh] = sum_i k_i outer v_i ; ksum[bh] = sum_i k_i
__global__ void __launch_bounds__(256) k_attn_kv(const bf16* __restrict__ qkv,
                                                 float* __restrict__ kv,
                                                 float* __restrict__ ksum) {
    int bh = blockIdx.x;
    int h = bh & (NH - 1), bc = bh >> 3;
    __shared__ float sk[16][HD];
    __shared__ float sv[16][HD];
    int tid = threadIdx.x;
    float acc[9];
    #pragma unroll
    for (int p = 0; p < 9; p++) acc[p] = 0.f;
    float ks = 0.f;
    int base = tid * 9;
    int dp[9], ep[9];
    #pragma unroll
    for (int p = 0; p < 9; p++) { dp[p] = (base + p) / HD; ep[p] = (base + p) % HD; }

    for (int c = 0; c < GS / 16; c++) {
        int tt0 = bc * GS + c * 16;
        #pragma unroll
        for (int r = 0; r < 3; r++) {
            int j = r * 256 + tid;
            int ti = j / HD, d = j % HD;
            size_t row = (size_t)(tt0 + ti) * QS + h * HD + d;
            sk[ti][d] = __bfloat162float(qkv[row + D]);
            sv[ti][d] = __bfloat162float(qkv[row + 2 * D]);
        }
        __syncthreads();
        #pragma unroll 4
        for (int ti = 0; ti < 16; ti++) {
            #pragma unroll
            for (int p = 0; p < 9; p++) acc[p] += sk[ti][dp[p]] * sv[ti][ep[p]];
        }
        if (tid < HD) {
            #pragma unroll 4
            for (int ti = 0; ti < 16; ti++) ks += sk[ti][tid];
        }
        __syncthreads();
    }
    #pragma unroll
    for (int p = 0; p < 9; p++) kv[(size_t)bh * HD * HD + base + p] = acc[p];
    if (tid < HD) ksum[bh * HD + tid] = ks;
}

// out[t,h,e] = (q . kv[:,e]) / (q . ksum + 1e-8), bf16 output
__global__ void __launch_bounds__(256) k_attn_apply(const bf16* __restrict__ qkv,
                                                    const float* __restrict__ kv,
                                                    const float* __restrict__ ksum,
                                                    bf16* __restrict__ out) {
    int bh = blockIdx.x;
    int tile = blockIdx.y;
    int h = bh & (NH - 1), bc = bh >> 3;
    __shared__ float skv[HD * HD];
    __shared__ float sks[HD];
    __shared__ float sq[16][HD];
    int tid = threadIdx.x;
    for (int i = tid; i < HD * HD; i += 256) skv[i] = kv[(size_t)bh * HD * HD + i];
    if (tid < HD) sks[tid] = ksum[bh * HD + tid];
    __syncthreads();
    int t0 = bc * GS + tile * 64;
    for (int sub = 0; sub < 4; sub++) {
        int tt0 = t0 + sub * 16;
        #pragma unroll
        for (int r = 0; r < 3; r++) {
            int j = r * 256 + tid;
            int ti = j / HD, d = j % HD;
            sq[ti][d] = __bfloat162float(qkv[(size_t)(tt0 + ti) * QS + h * HD + d]);
        }
        __syncthreads();
        #pragma unroll
        for (int r = 0; r < 3; r++) {
            int j = r * 256 + tid;
            int ti = j / HD, e = j % HD;
            float num = 0.f, den = 0.f;
            #pragma unroll
            for (int d = 0; d < HD; d++) {
                float qq = sq[ti][d];
                num += qq * skv[d * HD + e];
                den += qq * sks[d];
            }
            out[(size_t)(tt0 + ti) * D + h * HD + e] = __float2bfloat16(num / (den + 1e-8f));
        }
        __syncthreads();
    }
}

// x2 = A2[b,d]*wi + C2[b,d], bf16 output
__global__ void k_x2(const float* __restrict__ wi, const float* __restrict__ A,
                     const float* __restrict__ C, bf16* __restrict__ x2) {
    size_t idx = (size_t)blockIdx.x * 256 + threadIdx.x;
    int t = (int)(idx / D), d = (int)(idx % D);
    int b = t >> 12;
    x2[idx] = __float2bfloat16(A[b * D + d] * wi[idx] + C[b * D + d]);
}

// out[b,d,pix] = image[b,d,pix] + wif[token(pix), d] * final_scalar[d]
__global__ void __launch_bounds__(256) k_final_t(
        const float* __restrict__ img, const float* __restrict__ wif,
        const int* __restrict__ invp, const float* __restrict__ fs,
        float* __restrict__ out) {
    __shared__ float tile[64][65];
    __shared__ int sinv[64];
    int p0 = blockIdx.x * 64, d0 = blockIdx.y * 64, b = blockIdx.z;
    int tid = threadIdx.x;
    if (tid < 64) sinv[tid] = invp[p0 + tid];
    __syncthreads();
    #pragma unroll
    for (int l = 0; l < 4; l++) {
        int j = tid + l * 256;
        int jp = j >> 4, i4 = (j & 15) * 4;
        int t = sinv[jp];
        float4 v = *(const float4*)(wif + ((size_t)(b * NP + t)) * D + d0 + i4);
        tile[i4 + 0][jp] = v.x; tile[i4 + 1][jp] = v.y;
        tile[i4 + 2][jp] = v.z; tile[i4 + 3][jp] = v.w;
    }
    __syncthreads();
    #pragma unroll
    for (int l = 0; l < 4; l++) {
        int j = tid + l * 256;
        int i = j >> 4, q = (j & 15) * 4;
        size_t o = ((size_t)(b * D + d0 + i)) * NP + p0 + q;
        float4 im4 = *(const float4*)(img + o);
        float f = fs[d0 + i];
        float4 r;
        r.x = im4.x + tile[i][q + 0] * f;
        r.y = im4.y + tile[i][q + 1] * f;
        r.z = im4.z + tile[i][q + 2] * f;
        r.w = im4.w + tile[i][q + 3] * f;
        *(float4*)(out + o) = r;
    }
}

// ---------------- driver ----------------------------------------------------
extern "C" void kernel_launch(void* const* d_in, const int* in_sizes, int n_in,
                              void* d_out, int out_size) {
    const float* image  = (const float*)d_in[0];
    const float* film   = (const float*)d_in[1];
    const int*   perm   = (const int*)d_in[2];
    const float* Wq = (const float*)d_in[3];  const float* bq = (const float*)d_in[4];
    const float* Wk = (const float*)d_in[5];  const float* bk = (const float*)d_in[6];
    const float* Wv = (const float*)d_in[7];  const float* bv = (const float*)d_in[8];
    const float* Wo = (const float*)d_in[9];  const float* bo = (const float*)d_in[10];
    const float* lnq_g = (const float*)d_in[11]; const float* lnq_b = (const float*)d_in[12];
    const float* lnk_g = (const float*)d_in[13]; const float* lnk_b = (const float*)d_in[14];
    const float* ada1_W = (const float*)d_in[15]; const float* ada1_b = (const float*)d_in[16];
    const float* grn1_g = (const float*)d_in[17]; const float* grn1_b = (const float*)d_in[18];
    const float* ada2_W = (const float*)d_in[19]; const float* ada2_b = (const float*)d_in[20];
    const float* grn2_g = (const float*)d_in[21]; const float* grn2_b = (const float*)d_in[22];
    const float* conv1_W = (const float*)d_in[23]; const float* conv1_b = (const float*)d_in[24];
    const float* conv2_W = (const float*)d_in[25]; const float* conv2_b = (const float*)d_in[26];
    const float* cs  = (const float*)d_in[27];
    const float* ffs = (const float*)d_in[28];
    const float* fs  = (const float*)d_in[29];
    float* out = (float*)d_out;

    float *p_gb1, *p_gb2, *p_gx, *p_gm, *p_A2, *p_C2, *p_gx2sq;
    int* p_invp;
    float *p_imtok, *p_wi, *p_wif, *p_kv, *p_ks, *p_bqkv;
    bf16 *p_qkv16, *p_xg16, *p_att16, *p_x216, *p_h116;
    bf16 *p_wqkv16, *p_wo16, *p_c1w16, *p_c2w16;
    cudaGetSymbolAddress((void**)&p_gb1, g_gb1);
    cudaGetSymbolAddress((void**)&p_gb2, g_gb2);
    cudaGetSymbolAddress((void**)&p_gx, g_gx);
    cudaGetSymbolAddress((void**)&p_gm, g_gm);
    cudaGetSymbolAddress((void**)&p_A2, g_A2);
    cudaGetSymbolAddress((void**)&p_C2, g_C2);
    cudaGetSymbolAddress((void**)&p_gx2sq, g_gx2sq);
    cudaGetSymbolAddress((void**)&p_invp, g_invp);
    cudaGetSymbolAddress((void**)&p_imtok, g_imtok);
    cudaGetSymbolAddress((void**)&p_wi, g_wi);
    cudaGetSymbolAddress((void**)&p_wif, g_wif);
    cudaGetSymbolAddress((void**)&p_kv, g_kv);
    cudaGetSymbolAddress((void**)&p_ks, g_ks);
    cudaGetSymbolAddress((void**)&p_bqkv, g_bqkv);
    cudaGetSymbolAddress((void**)&p_qkv16, g_qkv16);
    cudaGetSymbolAddress((void**)&p_xg16, g_xg16);
    cudaGetSymbolAddress((void**)&p_att16, g_att16);
    cudaGetSymbolAddress((void**)&p_x216, g_x216);
    cudaGetSymbolAddress((void**)&p_h116, g_h116);
    cudaGetSymbolAddress((void**)&p_wqkv16, g_wqkv16);
    cudaGetSymbolAddress((void**)&p_wo16, g_wo16);
    cudaGetSymbolAddress((void**)&p_c1w16, g_c1w16);
    cudaGetSymbolAddress((void**)&p_c2w16, g_c2w16);

    cudaFuncSetAttribute((const void*)gemm_mma<bf16,false,false,false>,
                         cudaFuncAttributeMaxDynamicSharedMemorySize, GEMM_SMEM);
    cudaFuncSetAttribute((const void*)gemm_mma<float,false,true,true>,
                         cudaFuncAttributeMaxDynamicSharedMemorySize, GEMM_SMEM);
    cudaFuncSetAttribute((const void*)gemm_mma<bf16,true,false,false>,
                         cudaFuncAttributeMaxDynamicSharedMemorySize, GEMM_SMEM);
    cudaFuncSetAttribute((const void*)gemm_mma<float,false,true,false>,
                         cudaFuncAttributeMaxDynamicSharedMemorySize, GEMM_SMEM);

    // launch 0: all prep + film
    k_prep<<<(PREP_TOT + 255) / 256, 256>>>(Wq, Wk, Wv, Wo, conv1_W, conv2_W,
        bq, bk, bv, perm, film, ada1_W, ada1_b, ada2_W, ada2_b,
        p_wqkv16, p_wo16, p_c1w16, p_c2w16,
        p_bqkv, p_gx2sq, p_gm, p_invp, p_gb1, p_gb2);
    // launch 1: gx + batch mean
    k_gx_img<<<B * D, 256>>>(image, p_gx, p_gm);
    // launch 2: gather with inline adaLN1 coefficients
    k_gather_t<<<dim3(NP/64, D/64, B), 256>>>(image, p_invp, p_gx, p_gm,
        grn1_g, grn1_b, p_gb1, p_imtok, p_xg16);
    // launch 3: packed QKV GEMM  <-- profiled launch
    gemm_mma<bf16,false,false,false><<<dim3(QS/128, T/128), 256, GEMM_SMEM>>>(
        p_xg16, p_wqkv16, p_bqkv, nullptr, nullptr, p_qkv16, nullptr, T, QS, D);

    k_lnelu<<<dim3(T/8, 2), 256>>>(p_qkv16, lnq_g, lnq_b, lnk_g, lnk_b);

    k_attn_kv<<<B * NC * NH, 256>>>(p_qkv16, p_kv, p_ks);
    k_attn_apply<<<dim3(B * NC * NH, 16), 256>>>(p_qkv16, p_kv, p_ks, p_att16);

    // wi = imtok + (attn@Wo^T + bo) * cs ; also gx2sq += wi^2
    gemm_mma<float,false,true,true><<<dim3(3, T/128), 256, GEMM_SMEM>>>(
        p_att16, p_wo16, bo, p_imtok, cs, p_wi, p_gx2sq, T, D, D);

    k_gmean_coef<<<B, 384>>>(p_gx2sq, grn2_g, grn2_b, p_gb2, p_A2, p_C2);
    k_x2<<<(int)(((size_t)T*D) / 256), 256>>>(p_wi, p_A2, p_C2, p_x216);

    // h1 = silu(x2 @ conv1^T + b1)
    gemm_mma<bf16,true,false,false><<<dim3(12, T/128), 256, GEMM_SMEM>>>(
        p_x216, p_c1w16, conv1_b, nullptr, nullptr, p_h116, nullptr, T, D4, D);
    // wif = wi + (h1 @ conv2^T + b2) * ffs
    gemm_mma<float,false,true,false><<<dim3(3, T/128), 256, GEMM_SMEM>>>(
        p_h116, p_c2w16, conv2_b, p_wi, ffs, p_wif, nullptr, T, D, D4);

    k_final_t<<<dim3(NP/64, D/64, B), 256>>>(image, p_wif, p_invp, fs, out);
}